// round 17
// baseline (speedup 1.0000x reference)
#include <cuda_runtime.h>
#include <math.h>
#include <stdint.h>

#define TLEN  32000
#define BATCH 8
#define RES   32
#define SKIPC 32
#define TT    128
#define TLT   256   // threads for k_layer (8 warps)

typedef unsigned long long ull;

// ==================== helpers ==============================================
__device__ __forceinline__ uint32_t smem_u32(const void* p) {
    uint32_t a;
    asm("{ .reg .u64 t; cvta.to.shared.u64 t, %1; cvt.u32.u64 %0, t; }" : "=r"(a) : "l"(p));
    return a;
}
__device__ __forceinline__ void sts32(uint32_t a, uint32_t v) {
    asm volatile("st.shared.b32 [%0], %1;" :: "r"(a), "r"(v));
}
__device__ __forceinline__ void sts64f(uint32_t a, float x, float y) {
    asm volatile("st.shared.v2.f32 [%0], {%1, %2};" :: "r"(a), "f"(x), "f"(y));
}
__device__ __forceinline__ void lds128(uint4& v, uint32_t a) {
    asm volatile("ld.shared.v4.b32 {%0,%1,%2,%3}, [%4];"
                 : "=r"(v.x), "=r"(v.y), "=r"(v.z), "=r"(v.w) : "r"(a));
}
__device__ __forceinline__ void ldsm4(uint32_t& r0, uint32_t& r1, uint32_t& r2, uint32_t& r3,
                                      uint32_t addr) {
    asm volatile("ldmatrix.sync.aligned.m8n8.x4.shared.b16 {%0,%1,%2,%3}, [%4];"
                 : "=r"(r0), "=r"(r1), "=r"(r2), "=r"(r3) : "r"(addr));
}
// pack {lo=v0, hi=v1} as bf16x2 (RN)
__device__ __forceinline__ uint32_t pack_bf16x2(float v0, float v1) {
    uint32_t r;
    asm("cvt.rn.bf16x2.f32 %0, %1, %2;" : "=r"(r) : "f"(v1), "f"(v0));
    return r;
}
__device__ __forceinline__ void mma_bf16(float* c,
                                         uint32_t a0, uint32_t a1, uint32_t a2, uint32_t a3,
                                         uint32_t b0, uint32_t b1) {
    asm volatile("mma.sync.aligned.m16n8k16.row.col.f32.bf16.bf16.f32 "
                 "{%0,%1,%2,%3}, {%4,%5,%6,%7}, {%8,%9}, {%0,%1,%2,%3};"
                 : "+f"(c[0]), "+f"(c[1]), "+f"(c[2]), "+f"(c[3])
                 : "r"(a0), "r"(a1), "r"(a2), "r"(a3), "r"(b0), "r"(b1));
}
__device__ __forceinline__ float ftanh(float x) {
    float e = __expf(-2.f * fabsf(x));
    float r = __fdividef(1.f - e, 1.f + e);
    return copysignf(r, x);
}
__device__ __forceinline__ float fsigm(float x) {
    return __fdividef(1.f, 1.f + __expf(-x));
}
// split pair into bf16 hi pack + residual lo pack
__device__ __forceinline__ void split_pair(float v0, float v1, uint32_t& hi, uint32_t& lo) {
    hi = pack_bf16x2(v0, v1);
    float h0 = __uint_as_float((hi & 0xFFFFu) << 16);
    float h1 = __uint_as_float(hi & 0xFFFF0000u);
    lo = pack_bf16x2(v0 - h0, v1 - h1);
}
__device__ __forceinline__ float bfl(uint32_t x) { return __uint_as_float(x << 16); }
__device__ __forceinline__ float bfh(uint32_t x) { return __uint_as_float(x & 0xFFFF0000u); }

// ==================== device scratch =======================================
__device__ uint32_t g_bh0[BATCH * TLEN * 16];
__device__ uint32_t g_bl0[BATCH * TLEN * 16];
__device__ uint32_t g_bh1[BATCH * TLEN * 16];
__device__ uint32_t g_bl1[BATCH * TLEN * 16];
__device__ float g_skip[BATCH * TLEN * SKIPC];   // time-major [b][t][32]
__device__ float g_ts[BATCH * SKIPC * TLEN];     // channel-major for post conv
__device__ float g_p2[BATCH * 16 * TLEN];
__device__ float g_p3[BATCH * 8 * TLEN];
__device__ float g_p4[BATCH * 1 * TLEN];
__device__ uint32_t g_w1h[10][64 * 52];
__device__ uint32_t g_w1l[10][64 * 52];
__device__ uint32_t g_w2h[10][64 * 20];
__device__ uint32_t g_w2l[10][64 * 20];

// ==================== weight prep ==========================================
__global__ __launch_bounds__(TT) void k_wprep(const float* __restrict__ res_w1,
                                              const float* __restrict__ res_w2) {
    int L = blockIdx.x;
    const float* w1 = res_w1 + (size_t)L * 64 * 32 * 3;
    const float* w2 = res_w2 + (size_t)L * 64 * 32;
    int tid = threadIdx.x;
    for (int i = tid; i < 64 * 48; i += TT) {
        int oc = i / 48, pj = i % 48;
        int k0 = 2 * pj;
        int tap = k0 >> 5, ic = k0 & 31;
        float v0 = w1[oc * 96 + ic * 3 + tap];
        float v1 = w1[oc * 96 + (ic + 1) * 3 + tap];
        uint32_t hi, lo;
        split_pair(v0, v1, hi, lo);
        g_w1h[L][oc * 52 + pj] = hi;
        g_w1l[L][oc * 52 + pj] = lo;
    }
    for (int i = tid; i < 64 * 16; i += TT) {
        int oc = i / 16, icp = i % 16;
        float v0 = w2[oc * 32 + 2 * icp];
        float v1 = w2[oc * 32 + 2 * icp + 1];
        uint32_t hi, lo;
        split_pair(v0, v1, hi, lo);
        g_w2h[L][oc * 20 + icp] = hi;
        g_w2l[L][oc * 20 + icp] = lo;
    }
}

// ==================== front conv -> bf16 hi/lo t-major; zero skip ==========
__global__ __launch_bounds__(TT) void k_front(const float* __restrict__ x,
                                              const float* __restrict__ w) {
    int b = blockIdx.y;
    int t = blockIdx.x * TT + threadIdx.x;
    if (t >= TLEN) return;
    const float* xb = x + b * TLEN;
    float x0 = xb[t];
    float x1 = (t >= 1) ? xb[t - 1] : 0.f;
    float x2 = (t >= 2) ? xb[t - 2] : 0.f;
    size_t base = (size_t)(b * TLEN + t) * 16;
    float* sk = g_skip + (size_t)(b * TLEN + t) * 32;
#pragma unroll
    for (int p = 0; p < 16; p++) {
        int oc = 2 * p;
        float v0 = fmaf(w[oc * 3 + 0], x2, fmaf(w[oc * 3 + 1], x1, w[oc * 3 + 2] * x0));
        float v1 = fmaf(w[(oc + 1) * 3 + 0], x2,
                   fmaf(w[(oc + 1) * 3 + 1], x1, w[(oc + 1) * 3 + 2] * x0));
        uint32_t hi, lo;
        split_pair(v0, v1, hi, lo);
        g_bh0[base + p] = hi;
        g_bl0[base + p] = lo;
        sk[oc] = 0.f;
        sk[oc + 1] = 0.f;
    }
}

// ==================== residual layers ======================================
#define STRW 80
#define STRB 208
#define WB_BYTES (2 * 64 * STRB + 2 * 64 * STRW)   // 36864

// ---------- M=128 variant (used for d >= 128) ------------------------------
#define EXH 0
#define EXL 10240
#define EXS 20480

template <int MINB>
__global__ __launch_bounds__(TLT, MINB) void k_layer(const uint32_t* __restrict__ hinH,
                                                     const uint32_t* __restrict__ hinL,
                                                     uint32_t* __restrict__ houtH,
                                                     uint32_t* __restrict__ houtL,
                                                     const uint32_t* __restrict__ w1h,
                                                     const uint32_t* __restrict__ w1l,
                                                     const uint32_t* __restrict__ w2h,
                                                     const uint32_t* __restrict__ w2l,
                                                     int d) {
    extern __shared__ __align__(16) char smem[];
    uint32_t sb = smem_u32(smem);
    int tid = threadIdx.x;
    int wid = tid >> 5;
    int lid = tid & 31;
    int qr = lid >> 2;
    int qc = lid & 3;
    int b = blockIdx.y;
    int t0 = blockIdx.x * 128;
    int dstep = (d <= 128) ? d : 128;
    int nrows = 128 + 2 * dstep;
    uint32_t aBytes = (uint32_t)nrows * STRW;
    uint32_t oAL  = aBytes;
    uint32_t oBH  = 2 * aBytes;
    uint32_t oBL  = oBH + 64 * STRB;
    uint32_t oW2H = oBL + 64 * STRB;
    uint32_t oW2L = oW2H + 64 * STRW;

    {
        const uint4 zero4 = make_uint4(0, 0, 0, 0);
        int units = nrows * 2;
        for (int idx = tid; idx < units; idx += TLT) {
            int r = idx >> 1;
            int arr = idx & 1;
            int t;
            if (d <= 128) t = t0 - 2 * d + r;
            else          t = t0 - (2 - (r >> 7)) * d + (r & 127);
            uint32_t dst = (arr ? oAL : 0u) + (uint32_t)(r * STRW);
            if (t >= 0) {
                const uint4* s4 = reinterpret_cast<const uint4*>(
                    (arr ? hinL : hinH) + (size_t)(b * TLEN + t) * 16);
#pragma unroll
                for (int q = 0; q < 4; q++)
                    *reinterpret_cast<uint4*>(smem + dst + q * 16) = s4[q];
            } else {
#pragma unroll
                for (int q = 0; q < 4; q++)
                    *reinterpret_cast<uint4*>(smem + dst + q * 16) = zero4;
            }
        }
    }
    {
        const uint4* s1h = reinterpret_cast<const uint4*>(w1h);
        const uint4* s1l = reinterpret_cast<const uint4*>(w1l);
        uint4* d1h = reinterpret_cast<uint4*>(smem + oBH);
        uint4* d1l = reinterpret_cast<uint4*>(smem + oBL);
        for (int i = tid; i < 64 * 13; i += TLT) {
            d1h[i] = s1h[i];
            d1l[i] = s1l[i];
        }
        const uint4* s2h = reinterpret_cast<const uint4*>(w2h);
        const uint4* s2l = reinterpret_cast<const uint4*>(w2l);
        uint4* d2h = reinterpret_cast<uint4*>(smem + oW2H);
        uint4* d2l = reinterpret_cast<uint4*>(smem + oW2L);
        for (int i = tid; i < 64 * 5; i += TLT) {
            d2h[i] = s2h[i];
            d2l[i] = s2l[i];
        }
    }
    __syncthreads();

    float acc[8][4];
#pragma unroll
    for (int n = 0; n < 8; n++)
#pragma unroll
        for (int j = 0; j < 4; j++) acc[n][j] = 0.f;
    {
        int lr = lid & 7;
        int aRowOff = lr + ((lid >> 3) & 1) * 8;
        int aKOff = (lid >> 4) * 8;
        int bRowOff = lr + (lid >> 4) * 8;
        int bKOff = ((lid >> 3) & 1) * 8;
        uint32_t aBaseH = sb + (uint32_t)((16 * wid + aRowOff) * STRW + aKOff * 2);
        uint32_t aBaseL = aBaseH + oAL;
        uint32_t bH0 = sb + oBH + (uint32_t)(bRowOff * STRB + bKOff * 2);
        uint32_t bL0 = sb + oBL + (uint32_t)(bRowOff * STRB + bKOff * 2);
        uint32_t tapStride = (uint32_t)(dstep * STRW);
#pragma unroll
        for (int k = 0; k < 6; k++) {
            int tap = k >> 1;
            uint32_t aoff = (uint32_t)tap * tapStride + (uint32_t)((k & 1) * 32);
            uint32_t ka = (uint32_t)(k * 32);
            uint32_t ah0, ah1, ah2, ah3, al0, al1, al2, al3;
            ldsm4(ah0, ah1, ah2, ah3, aBaseH + aoff);
            ldsm4(al0, al1, al2, al3, aBaseL + aoff);
#pragma unroll
            for (int np = 0; np < 4; np++) {
                uint32_t off = (uint32_t)(16 * np * STRB) + ka;
                uint32_t bh0, bh1, bh2, bh3, bl0, bl1, bl2, bl3;
                ldsm4(bh0, bh1, bh2, bh3, bH0 + off);
                ldsm4(bl0, bl1, bl2, bl3, bL0 + off);
                mma_bf16(acc[2 * np],     ah0, ah1, ah2, ah3, bh0, bh1);
                mma_bf16(acc[2 * np + 1], ah0, ah1, ah2, ah3, bh2, bh3);
                mma_bf16(acc[2 * np],     al0, al1, al2, al3, bh0, bh1);
                mma_bf16(acc[2 * np + 1], al0, al1, al2, al3, bh2, bh3);
                mma_bf16(acc[2 * np],     ah0, ah1, ah2, ah3, bl0, bl1);
                mma_bf16(acc[2 * np + 1], ah0, ah1, ah2, ah3, bl2, bl3);
            }
        }
    }

    float gv[4][4];
#pragma unroll
    for (int n = 0; n < 4; n++)
#pragma unroll
        for (int j = 0; j < 4; j++)
            gv[n][j] = ftanh(acc[n][j]) * fsigm(acc[n + 4][j]);

    uint32_t aH[2][4], aL[2][4];
#pragma unroll
    for (int kk = 0; kk < 2; kk++) {
        split_pair(gv[2 * kk][0],     gv[2 * kk][1],     aH[kk][0], aL[kk][0]);
        split_pair(gv[2 * kk][2],     gv[2 * kk][3],     aH[kk][1], aL[kk][1]);
        split_pair(gv[2 * kk + 1][0], gv[2 * kk + 1][1], aH[kk][2], aL[kk][2]);
        split_pair(gv[2 * kk + 1][2], gv[2 * kk + 1][3], aH[kk][3], aL[kk][3]);
    }

    float acc2[8][4];
#pragma unroll
    for (int n = 0; n < 8; n++)
#pragma unroll
        for (int j = 0; j < 4; j++) acc2[n][j] = 0.f;
    {
        int lr = lid & 7;
        int bRowOff = lr + (lid >> 4) * 8;
        int bKOff = ((lid >> 3) & 1) * 8;
        uint32_t w2H0 = sb + oW2H + (uint32_t)(bRowOff * STRW + bKOff * 2);
        uint32_t w2L0 = sb + oW2L + (uint32_t)(bRowOff * STRW + bKOff * 2);
#pragma unroll
        for (int kk = 0; kk < 2; kk++) {
            uint32_t ka = (uint32_t)(kk * 32);
#pragma unroll
            for (int np = 0; np < 4; np++) {
                uint32_t off = (uint32_t)(16 * np * STRW) + ka;
                uint32_t bh0, bh1, bh2, bh3, bl0, bl1, bl2, bl3;
                ldsm4(bh0, bh1, bh2, bh3, w2H0 + off);
                ldsm4(bl0, bl1, bl2, bl3, w2L0 + off);
                mma_bf16(acc2[2 * np],     aH[kk][0], aH[kk][1], aH[kk][2], aH[kk][3], bh0, bh1);
                mma_bf16(acc2[2 * np + 1], aH[kk][0], aH[kk][1], aH[kk][2], aH[kk][3], bh2, bh3);
                mma_bf16(acc2[2 * np],     aL[kk][0], aL[kk][1], aL[kk][2], aL[kk][3], bh0, bh1);
                mma_bf16(acc2[2 * np + 1], aL[kk][0], aL[kk][1], aL[kk][2], aL[kk][3], bh2, bh3);
                mma_bf16(acc2[2 * np],     aH[kk][0], aH[kk][1], aH[kk][2], aH[kk][3], bl0, bl1);
                mma_bf16(acc2[2 * np + 1], aH[kk][0], aH[kk][1], aH[kk][2], aH[kk][3], bl2, bl3);
            }
        }
    }

    uint32_t rhi[2][4], rlo[2][4];
#pragma unroll
    for (int rh = 0; rh < 2; rh++) {
        int rowA = 16 * wid + qr + 8 * rh;
        uint32_t rbase = (uint32_t)((rowA + 2 * dstep) * STRW);
#pragma unroll
        for (int n = 0; n < 4; n++) {
            int c = 8 * n + 2 * qc;
            uint32_t hh = *reinterpret_cast<uint32_t*>(smem + rbase + c * 2);
            uint32_t ll = *reinterpret_cast<uint32_t*>(smem + oAL + rbase + c * 2);
            float r0 = bfl(hh) + bfl(ll) + acc2[n][2 * rh + 0];
            float r1 = bfh(hh) + bfh(ll) + acc2[n][2 * rh + 1];
            split_pair(r0, r1, rhi[rh][n], rlo[rh][n]);
        }
    }
    __syncthreads();

#pragma unroll
    for (int rh = 0; rh < 2; rh++) {
        int rowA = 16 * wid + qr + 8 * rh;
#pragma unroll
        for (int n = 0; n < 4; n++) {
            uint32_t w = (uint32_t)(rowA * 20 + 4 * n + qc) * 4;
            sts32(sb + EXH + w, rhi[rh][n]);
            sts32(sb + EXL + w, rlo[rh][n]);
        }
#pragma unroll
        for (int n = 4; n < 8; n++) {
            int c = 8 * (n - 4) + 2 * qc;
            uint32_t w = (uint32_t)(rowA * 36 + c) * 4;
            sts64f(sb + EXS + w, acc2[n][2 * rh + 0], acc2[n][2 * rh + 1]);
        }
    }
    __syncthreads();

    {
        int plane = tid >> 7;
        int idx = tid & 127;
        uint32_t exb = sb + (plane ? EXL : EXH);
        uint32_t* gout = plane ? houtL : houtH;
        size_t gb4 = (size_t)(b * TLEN + t0) * 4;
#pragma unroll
        for (int j = 0; j < 4; j++) {
            int g = idx + 128 * j;
            int row = g >> 2, q = g & 3;
            uint4 v;
            lds128(v, exb + (uint32_t)(row * 20 + q * 4) * 4);
            reinterpret_cast<uint4*>(gout)[gb4 + g] = v;
        }
        float4* skb = reinterpret_cast<float4*>(g_skip + (size_t)(b * TLEN + t0) * 32);
#pragma unroll
        for (int j = 0; j < 4; j++) {
            int g = tid + 256 * j;
            int row = g >> 3, q = g & 7;
            uint4 zv;
            lds128(zv, sb + EXS + (uint32_t)(row * 36 + q * 4) * 4);
            float4 s = skb[g];
            s.x += __uint_as_float(zv.x);
            s.y += __uint_as_float(zv.y);
            s.z += __uint_as_float(zv.z);
            s.w += __uint_as_float(zv.w);
            skb[g] = s;
        }
    }
}

// ---------- M=256 variant (d <= 64): B fragments reused across 2 m-tiles ----
#define EXH2 0          // hout hi plane: 256 rows x 20 words = 20480
#define EXL2 20480
#define EXS2 40960      // skip z: 256 rows x 36 words = 36864 (end 77824)

__global__ __launch_bounds__(TLT, 2) void k_layer256(const uint32_t* __restrict__ hinH,
                                                     const uint32_t* __restrict__ hinL,
                                                     uint32_t* __restrict__ houtH,
                                                     uint32_t* __restrict__ houtL,
                                                     const uint32_t* __restrict__ w1h,
                                                     const uint32_t* __restrict__ w1l,
                                                     const uint32_t* __restrict__ w2h,
                                                     const uint32_t* __restrict__ w2l,
                                                     int d) {
    extern __shared__ __align__(16) char smem[];
    uint32_t sb = smem_u32(smem);
    int tid = threadIdx.x;
    int wid = tid >> 5;
    int lid = tid & 31;
    int qr = lid >> 2;
    int qc = lid & 3;
    int b = blockIdx.y;
    int t0 = blockIdx.x * 256;
    int nrows = 256 + 2 * d;
    uint32_t aBytes = (uint32_t)nrows * STRW;
    uint32_t oAL  = aBytes;
    uint32_t oBH  = 2 * aBytes;
    uint32_t oBL  = oBH + 64 * STRB;
    uint32_t oW2H = oBL + 64 * STRB;
    uint32_t oW2L = oW2H + 64 * STRW;

    // ---- stage A window
    {
        const uint4 zero4 = make_uint4(0, 0, 0, 0);
        int units = nrows * 2;
        for (int idx = tid; idx < units; idx += TLT) {
            int r = idx >> 1;
            int arr = idx & 1;
            int t = t0 - 2 * d + r;
            uint32_t dst = (arr ? oAL : 0u) + (uint32_t)(r * STRW);
            if (t >= 0) {
                const uint4* s4 = reinterpret_cast<const uint4*>(
                    (arr ? hinL : hinH) + (size_t)(b * TLEN + t) * 16);
#pragma unroll
                for (int q = 0; q < 4; q++)
                    *reinterpret_cast<uint4*>(smem + dst + q * 16) = s4[q];
            } else {
#pragma unroll
                for (int q = 0; q < 4; q++)
                    *reinterpret_cast<uint4*>(smem + dst + q * 16) = zero4;
            }
        }
    }
    // ---- weights
    {
        const uint4* s1h = reinterpret_cast<const uint4*>(w1h);
        const uint4* s1l = reinterpret_cast<const uint4*>(w1l);
        uint4* d1h = reinterpret_cast<uint4*>(smem + oBH);
        uint4* d1l = reinterpret_cast<uint4*>(smem + oBL);
        for (int i = tid; i < 64 * 13; i += TLT) {
            d1h[i] = s1h[i];
            d1l[i] = s1l[i];
        }
        const uint4* s2h = reinterpret_cast<const uint4*>(w2h);
        const uint4* s2l = reinterpret_cast<const uint4*>(w2l);
        uint4* d2h = reinterpret_cast<uint4*>(smem + oW2H);
        uint4* d2l = reinterpret_cast<uint4*>(smem + oW2L);
        for (int i = tid; i < 64 * 5; i += TLT) {
            d2h[i] = s2h[i];
            d2l[i] = s2l[i];
        }
    }
    __syncthreads();

    // ---- conv GEMM: 2 m-tiles per warp, B frags reused
    float acc[2][8][4];
#pragma unroll
    for (int mt = 0; mt < 2; mt++)
#pragma unroll
        for (int n = 0; n < 8; n++)
#pragma unroll
            for (int j = 0; j < 4; j++) acc[mt][n][j] = 0.f;
    {
        int lr = lid & 7;
        int aRowOff = lr + ((lid >> 3) & 1) * 8;
        int aKOff = (lid >> 4) * 8;
        int bRowOff = lr + (lid >> 4) * 8;
        int bKOff = ((lid >> 3) & 1) * 8;
        uint32_t aBaseH = sb + (uint32_t)((32 * wid + aRowOff) * STRW + aKOff * 2);
        uint32_t aBaseL = aBaseH + oAL;
        uint32_t bH0 = sb + oBH + (uint32_t)(bRowOff * STRB + bKOff * 2);
        uint32_t bL0 = sb + oBL + (uint32_t)(bRowOff * STRB + bKOff * 2);
        uint32_t tapStride = (uint32_t)(d * STRW);
#pragma unroll
        for (int k = 0; k < 6; k++) {
            int tap = k >> 1;
            uint32_t aoff = (uint32_t)tap * tapStride + (uint32_t)((k & 1) * 32);
            uint32_t ka = (uint32_t)(k * 32);
            uint32_t ah[2][4], al[2][4];
            ldsm4(ah[0][0], ah[0][1], ah[0][2], ah[0][3], aBaseH + aoff);
            ldsm4(al[0][0], al[0][1], al[0][2], al[0][3], aBaseL + aoff);
            ldsm4(ah[1][0], ah[1][1], ah[1][2], ah[1][3], aBaseH + aoff + 16 * STRW);
            ldsm4(al[1][0], al[1][1], al[1][2], al[1][3], aBaseL + aoff + 16 * STRW);
#pragma unroll
            for (int np = 0; np < 4; np++) {
                uint32_t off = (uint32_t)(16 * np * STRB) + ka;
                uint32_t bh0, bh1, bh2, bh3, bl0, bl1, bl2, bl3;
                ldsm4(bh0, bh1, bh2, bh3, bH0 + off);
                ldsm4(bl0, bl1, bl2, bl3, bL0 + off);
#pragma unroll
                for (int mt = 0; mt < 2; mt++) {
                    mma_bf16(acc[mt][2 * np],     ah[mt][0], ah[mt][1], ah[mt][2], ah[mt][3], bh0, bh1);
                    mma_bf16(acc[mt][2 * np + 1], ah[mt][0], ah[mt][1], ah[mt][2], ah[mt][3], bh2, bh3);
                    mma_bf16(acc[mt][2 * np],     al[mt][0], al[mt][1], al[mt][2], al[mt][3], bh0, bh1);
                    mma_bf16(acc[mt][2 * np + 1], al[mt][0], al[mt][1], al[mt][2], al[mt][3], bh2, bh3);
                    mma_bf16(acc[mt][2 * np],     ah[mt][0], ah[mt][1], ah[mt][2], ah[mt][3], bl0, bl1);
                    mma_bf16(acc[mt][2 * np + 1], ah[mt][0], ah[mt][1], ah[mt][2], ah[mt][3], bl2, bl3);
                }
            }
        }
    }

    // ---- gating in registers -> A fragments per m-tile
    uint32_t gaH[2][2][4], gaL[2][2][4];
#pragma unroll
    for (int mt = 0; mt < 2; mt++) {
        float gv[4][4];
#pragma unroll
        for (int n = 0; n < 4; n++)
#pragma unroll
            for (int j = 0; j < 4; j++)
                gv[n][j] = ftanh(acc[mt][n][j]) * fsigm(acc[mt][n + 4][j]);
#pragma unroll
        for (int kk = 0; kk < 2; kk++) {
            split_pair(gv[2 * kk][0],     gv[2 * kk][1],     gaH[mt][kk][0], gaL[mt][kk][0]);
            split_pair(gv[2 * kk][2],     gv[2 * kk][3],     gaH[mt][kk][1], gaL[mt][kk][1]);
            split_pair(gv[2 * kk + 1][0], gv[2 * kk + 1][1], gaH[mt][kk][2], gaL[mt][kk][2]);
            split_pair(gv[2 * kk + 1][2], gv[2 * kk + 1][3], gaH[mt][kk][3], gaL[mt][kk][3]);
        }
    }

    // ---- 1x1 GEMM: W2 frags reused across m-tiles
    float acc2[2][8][4];
#pragma unroll
    for (int mt = 0; mt < 2; mt++)
#pragma unroll
        for (int n = 0; n < 8; n++)
#pragma unroll
            for (int j = 0; j < 4; j++) acc2[mt][n][j] = 0.f;
    {
        int lr = lid & 7;
        int bRowOff = lr + (lid >> 4) * 8;
        int bKOff = ((lid >> 3) & 1) * 8;
        uint32_t w2H0 = sb + oW2H + (uint32_t)(bRowOff * STRW + bKOff * 2);
        uint32_t w2L0 = sb + oW2L + (uint32_t)(bRowOff * STRW + bKOff * 2);
#pragma unroll
        for (int kk = 0; kk < 2; kk++) {
            uint32_t ka = (uint32_t)(kk * 32);
#pragma unroll
            for (int np = 0; np < 4; np++) {
                uint32_t off = (uint32_t)(16 * np * STRW) + ka;
                uint32_t bh0, bh1, bh2, bh3, bl0, bl1, bl2, bl3;
                ldsm4(bh0, bh1, bh2, bh3, w2H0 + off);
                ldsm4(bl0, bl1, bl2, bl3, w2L0 + off);
#pragma unroll
                for (int mt = 0; mt < 2; mt++) {
                    mma_bf16(acc2[mt][2 * np],     gaH[mt][kk][0], gaH[mt][kk][1], gaH[mt][kk][2], gaH[mt][kk][3], bh0, bh1);
                    mma_bf16(acc2[mt][2 * np + 1], gaH[mt][kk][0], gaH[mt][kk][1], gaH[mt][kk][2], gaH[mt][kk][3], bh2, bh3);
                    mma_bf16(acc2[mt][2 * np],     gaL[mt][kk][0], gaL[mt][kk][1], gaL[mt][kk][2], gaL[mt][kk][3], bh0, bh1);
                    mma_bf16(acc2[mt][2 * np + 1], gaL[mt][kk][0], gaL[mt][kk][1], gaL[mt][kk][2], gaL[mt][kk][3], bh2, bh3);
                    mma_bf16(acc2[mt][2 * np],     gaH[mt][kk][0], gaH[mt][kk][1], gaH[mt][kk][2], gaH[mt][kk][3], bl0, bl1);
                    mma_bf16(acc2[mt][2 * np + 1], gaH[mt][kk][0], gaH[mt][kk][1], gaH[mt][kk][2], gaH[mt][kk][3], bl2, bl3);
                }
            }
        }
    }

    // ---- epilogue phase A: residual (window row m + 2d)
    uint32_t rhi[2][2][4], rlo[2][2][4];
#pragma unroll
    for (int mt = 0; mt < 2; mt++) {
#pragma unroll
        for (int rh = 0; rh < 2; rh++) {
            int rowA = 32 * wid + 16 * mt + qr + 8 * rh;
            uint32_t rbase = (uint32_t)((rowA + 2 * d) * STRW);
#pragma unroll
            for (int n = 0; n < 4; n++) {
                int c = 8 * n + 2 * qc;
                uint32_t hh = *reinterpret_cast<uint32_t*>(smem + rbase + c * 2);
                uint32_t ll = *reinterpret_cast<uint32_t*>(smem + oAL + rbase + c * 2);
                float r0 = bfl(hh) + bfl(ll) + acc2[mt][n][2 * rh + 0];
                float r1 = bfh(hh) + bfh(ll) + acc2[mt][n][2 * rh + 1];
                split_pair(r0, r1, rhi[mt][rh][n], rlo[mt][rh][n]);
            }
        }
    }
    __syncthreads();

    // ---- phase B: STS exchange
#pragma unroll
    for (int mt = 0; mt < 2; mt++) {
#pragma unroll
        for (int rh = 0; rh < 2; rh++) {
            int rowA = 32 * wid + 16 * mt + qr + 8 * rh;
#pragma unroll
            for (int n = 0; n < 4; n++) {
                uint32_t w = (uint32_t)(rowA * 20 + 4 * n + qc) * 4;
                sts32(sb + EXH2 + w, rhi[mt][rh][n]);
                sts32(sb + EXL2 + w, rlo[mt][rh][n]);
            }
#pragma unroll
            for (int n = 4; n < 8; n++) {
                int c = 8 * (n - 4) + 2 * qc;
                uint32_t w = (uint32_t)(rowA * 36 + c) * 4;
                sts64f(sb + EXS2 + w, acc2[mt][n][2 * rh + 0], acc2[mt][n][2 * rh + 1]);
            }
        }
    }
    __syncthreads();

    // ---- phase C: coalesced copy-out (256 rows)
    {
        int plane = tid >> 7;
        int idx = tid & 127;
        uint32_t exb = sb + (plane ? EXL2 : EXH2);
        uint32_t* gout = plane ? houtL : houtH;
        size_t gb4 = (size_t)(b * TLEN + t0) * 4;
#pragma unroll
        for (int j = 0; j < 8; j++) {
            int g = idx + 128 * j;
            int row = g >> 2, q = g & 3;
            uint4 v;
            lds128(v, exb + (uint32_t)(row * 20 + q * 4) * 4);
            reinterpret_cast<uint4*>(gout)[gb4 + g] = v;
        }
        float4* skb = reinterpret_cast<float4*>(g_skip + (size_t)(b * TLEN + t0) * 32);
#pragma unroll
        for (int j = 0; j < 8; j++) {
            int g = tid + 256 * j;
            int row = g >> 3, q = g & 7;
            uint4 zv;
            lds128(zv, sb + EXS2 + (uint32_t)(row * 36 + q * 4) * 4);
            float4 s = skb[g];
            s.x += __uint_as_float(zv.x);
            s.y += __uint_as_float(zv.y);
            s.z += __uint_as_float(zv.z);
            s.w += __uint_as_float(zv.w);
            skb[g] = s;
        }
    }
}

// ==================== tanh over skip (t-major -> channel-major) ============
__global__ __launch_bounds__(TT) void k_tanhskip() {
    int b = blockIdx.y;
    int t = blockIdx.x * TT + threadIdx.x;
    if (t >= TLEN) return;
    const float* sk = g_skip + (size_t)(b * TLEN + t) * 32;
#pragma unroll
    for (int c = 0; c < SKIPC; c++)
        g_ts[(b * SKIPC + c) * TLEN + t] = ftanh(sk[c]);
}

// ==================== generic causal k=3 conv + tanh =======================
template <int IC, int OC>
__global__ __launch_bounds__(TT) void k_conv3tanh(const float* __restrict__ in,
                                                  float* __restrict__ out,
                                                  const float* __restrict__ w) {
    __shared__ float ws[3][IC][OC];
    int tid = threadIdx.x;
    for (int i = tid; i < OC * IC * 3; i += TT) {
        int oc = i / (IC * 3), r = i % (IC * 3), ic = r / 3, k = r % 3;
        ws[k][ic][oc] = w[i];
    }
    __syncthreads();

    int b = blockIdx.y;
    int t = blockIdx.x * TT + tid;
    if (t >= TLEN) return;
    const float* ib = in + b * IC * TLEN;

    float acc[OC];
#pragma unroll
    for (int o = 0; o < OC; o++) acc[o] = 0.f;
#pragma unroll
    for (int k = 0; k < 3; k++) {
        int tt = t - (2 - k);
        if (tt >= 0) {
#pragma unroll
            for (int ic = 0; ic < IC; ic++) {
                float v = ib[ic * TLEN + tt];
#pragma unroll
                for (int o = 0; o < OC; o++)
                    acc[o] = fmaf(v, ws[k][ic][o], acc[o]);
            }
        }
    }
    float* ob = out + b * OC * TLEN;
#pragma unroll
    for (int o = 0; o < OC; o++)
        ob[o * TLEN + t] = ftanh(acc[o]);
}

// ==================== Volterra head ========================================
__global__ __launch_bounds__(TT) void k_vnn(const float* __restrict__ w1,
                                            const float* __restrict__ w2,
                                            float* __restrict__ out) {
    int b = blockIdx.y;
    int t = blockIdx.x * TT + threadIdx.x;
    if (t >= TLEN) return;
    const float* pb = g_p4 + b * TLEN;

    float pv[16];
#pragma unroll
    for (int k = 0; k < 16; k++) {
        int tt = t - (15 - k);
        pv[k] = (tt >= 0) ? pb[tt] : 0.f;
    }
    float lin = 0.f;
#pragma unroll
    for (int k = 0; k < 16; k++) lin = fmaf(w1[k], pv[k], lin);

    float x2[6];
#pragma unroll
    for (int j = 0; j < 6; j++) {
        float a = 0.f;
#pragma unroll
        for (int k = 0; k < 16; k++) a = fmaf(w2[j * 16 + k], pv[k], a);
        x2[j] = a;
    }
    float quad = x2[0] * x2[3] + x2[1] * x2[4] + x2[2] * x2[5];
    out[b * TLEN + t] = lin + quad;
}

// ==================== host launch ==========================================
extern "C" void kernel_launch(void* const* d_in, const int* in_sizes, int n_in,
                              void* d_out, int out_size) {
    const float* x       = (const float*)d_in[0];
    const float* conv1_w = (const float*)d_in[1];
    const float* res_w1  = (const float*)d_in[2];
    const float* res_w2  = (const float*)d_in[3];
    const float* post2_w = (const float*)d_in[4];
    const float* post3_w = (const float*)d_in[5];
    const float* post4_w = (const float*)d_in[6];
    const float* vnn1_w  = (const float*)d_in[7];
    const float* vnn2_w  = (const float*)d_in[8];
    float* out = (float*)d_out;

    uint32_t *bh0, *bl0, *bh1, *bl1;
    uint32_t *w1h, *w1l, *w2h, *w2l;
    float *tsp, *p2p, *p3p, *p4p;
    cudaGetSymbolAddress((void**)&bh0, g_bh0);
    cudaGetSymbolAddress((void**)&bl0, g_bl0);
    cudaGetSymbolAddress((void**)&bh1, g_bh1);
    cudaGetSymbolAddress((void**)&bl1, g_bl1);
    cudaGetSymbolAddress((void**)&w1h, g_w1h);
    cudaGetSymbolAddress((void**)&w1l, g_w1l);
    cudaGetSymbolAddress((void**)&w2h, g_w2h);
    cudaGetSymbolAddress((void**)&w2l, g_w2l);
    cudaGetSymbolAddress((void**)&tsp, g_ts);
    cudaGetSymbolAddress((void**)&p2p, g_p2);
    cudaGetSymbolAddress((void**)&p3p, g_p3);
    cudaGetSymbolAddress((void**)&p4p, g_p4);

    cudaFuncSetAttribute(k_layer<2>, cudaFuncAttributeMaxDynamicSharedMemorySize,
                         160 * 384 + WB_BYTES);           // 98304
    cudaFuncSetAttribute(k_layer256, cudaFuncAttributeMaxDynamicSharedMemorySize,
                         160 * (256 + 128) + WB_BYTES);   // d<=64 -> 98304

    dim3 grid128(TLEN / 128, BATCH);   // 250 x 8
    dim3 grid256(TLEN / 256, BATCH);   // 125 x 8

    k_wprep<<<10, TT>>>(res_w1, res_w2);
    k_front<<<grid128, TT>>>(x, conv1_w);

    const uint32_t *hinH = bh0, *hinL = bl0;
    uint32_t *houtH = bh1, *houtL = bl1;
    for (int s = 0; s < 2; s++) {
        for (int i = 0; i < 10; i++) {
            int d = 1 << i;
            const uint32_t* a1 = w1h + (size_t)i * 64 * 52;
            const uint32_t* a2 = w1l + (size_t)i * 64 * 52;
            const uint32_t* a3 = w2h + (size_t)i * 64 * 20;
            const uint32_t* a4 = w2l + (size_t)i * 64 * 20;
            if (d <= 64) {
                size_t smemBytes = (size_t)160 * (256 + 2 * d) + WB_BYTES;
                k_layer256<<<grid256, TLT, smemBytes>>>(hinH, hinL, houtH, houtL,
                                                        a1, a2, a3, a4, d);
            } else {
                int dstep = (d <= 128) ? d : 128;
                size_t smemBytes = (size_t)160 * (128 + 2 * dstep) + WB_BYTES;
                k_layer<2><<<grid128, TLT, smemBytes>>>(hinH, hinL, houtH, houtL,
                                                        a1, a2, a3, a4, d);
            }
            const uint32_t* th = houtH; const uint32_t* tl = houtL;
            houtH = (uint32_t*)hinH; houtL = (uint32_t*)hinL;
            hinH = th; hinL = tl;
        }
    }

    k_tanhskip<<<grid128, TT>>>();
    k_conv3tanh<32, 16><<<grid128, TT>>>(tsp, p2p, post2_w);
    k_conv3tanh<16, 8><<<grid128, TT>>>(p2p, p3p, post3_w);
    k_conv3tanh<8, 1><<<grid128, TT>>>(p3p, p4p, post4_w);
    k_vnn<<<grid128, TT>>>(vnn1_w, vnn2_w, out);
}